// round 8
// baseline (speedup 1.0000x reference)
#include <cuda_runtime.h>
#include <cstdint>

// ---------------------------------------------------------------------------
// W8A8B32O32 Linear: D[m,n] = round(alpha * sum_k x[m,k]*W[n,k] + beta*bias[n])
// M=8192, K=4096, N=4096. Inputs int32 holding int8-range values.
//
// ROUND 8: resubmission of round 7 (infra failed; kernel never ran).
// Minimal-trust dp4a kernel; output stored as FLOAT32 (rounded integer value
// as float). Theory under test: the harness's __output__ dtype is float32 —
// int32 bit patterns of small negative results read as float32 NaNs, which
// explains the constant rel_err=nan across five different kernels.
// ---------------------------------------------------------------------------

#define M_DIM 8192
#define N_DIM 4096
#define K_DIM 4096

#define BM 128
#define BN 128
#define BKW 16          // k-words per tile (16 x 4 int8 = 64 k-elements)
#define KT (K_DIM / 64) // 64 k-tiles
#define ROWW 17         // padded smem row stride in 32-bit words

__global__ void __launch_bounds__(256, 2) gemm_dp4a(
    const int* __restrict__ x, const int* __restrict__ w,
    const int* __restrict__ bias, const float* __restrict__ alphap,
    const float* __restrict__ betap, float* __restrict__ out) {
    __shared__ uint32_t sA[BM * ROWW];   // 128 rows x 16 packed words (+1 pad)
    __shared__ uint32_t sB[BN * ROWW];

    const int tid = threadIdx.x;
    const int ty = tid >> 4;             // 0..15  (row group)
    const int tx = tid & 15;             // 0..15  (col group)
    const int m0 = blockIdx.y * BM;
    const int n0 = blockIdx.x * BN;

    // pack 4 int32 (int8-range values) into one word of 4 int8
    auto pk = [](int4 v) -> uint32_t {
        uint32_t lo = __byte_perm((uint32_t)v.x, (uint32_t)v.y, 0x0040);
        uint32_t hi = __byte_perm((uint32_t)v.z, (uint32_t)v.w, 0x0040);
        return __byte_perm(lo, hi, 0x5410);
    };

    int acc[8][8];
    #pragma unroll
    for (int r = 0; r < 8; r++)
        #pragma unroll
        for (int c = 0; c < 8; c++) acc[r][c] = 0;

    for (int kt = 0; kt < KT; kt++) {
        const int koff = kt * 64;        // k-element offset of this tile

        // Load + pack this tile: 2048 packed words per operand, 8 per thread.
        #pragma unroll
        for (int i = 0; i < 8; i++) {
            const int idx = tid + 256 * i;
            const int row = idx >> 4;
            const int wq = idx & 15;
            const int4 va = *reinterpret_cast<const int4*>(
                x + (size_t)(m0 + row) * K_DIM + koff + wq * 4);
            sA[row * ROWW + wq] = pk(va);
            const int4 vb = *reinterpret_cast<const int4*>(
                w + (size_t)(n0 + row) * K_DIM + koff + wq * 4);
            sB[row * ROWW + wq] = pk(vb);
        }
        __syncthreads();

        // Compute: thread (ty,tx) owns rows {ty+16r}, cols {tx+16c}.
        #pragma unroll 4
        for (int wq = 0; wq < BKW; wq++) {
            uint32_t a[8], b[8];
            #pragma unroll
            for (int r = 0; r < 8; r++) a[r] = sA[(ty + 16 * r) * ROWW + wq];
            #pragma unroll
            for (int c = 0; c < 8; c++) b[c] = sB[(tx + 16 * c) * ROWW + wq];
            #pragma unroll
            for (int r = 0; r < 8; r++)
                #pragma unroll
                for (int c = 0; c < 8; c++)
                    acc[r][c] = __dp4a((int)a[r], (int)b[c], acc[r][c]);
        }
        __syncthreads();
    }

    // ------------------------- epilogue --------------------------------
    // round(alpha*acc + beta*bias) with round-to-nearest-even, then store the
    // rounded integer VALUE as float32 (exact for |v| < 2^24).
    const float av = *alphap;
    const float bv = *betap;
    #pragma unroll
    for (int c = 0; c < 8; c++) {
        const int n = n0 + tx + 16 * c;
        const float bb = __fmul_rn(bv, (float)bias[n]);
        #pragma unroll
        for (int r = 0; r < 8; r++) {
            const int m = m0 + ty + 16 * r;
            const int v = __float2int_rn(__fadd_rn(__fmul_rn(av, (float)acc[r][c]), bb));
            out[(size_t)m * N_DIM + n] = (float)v;
        }
    }
}

// ---------------------------------------------------------------------------
extern "C" void kernel_launch(void* const* d_in, const int* in_sizes, int n_in,
                              void* d_out, int out_size) {
    // Bind inputs BY SIZE (robust to metadata ordering). alpha precedes beta
    // in both dict order and alphabetical order.
    const int* x = nullptr;       // 8192*4096 = 33,554,432
    const int* w = nullptr;       // 4096*4096 = 16,777,216
    const int* bias = nullptr;    // 4096
    const float* alpha = nullptr; // 1 (first size-1 input)
    const float* beta = nullptr;  // 1 (second size-1 input)
    for (int i = 0; i < n_in; i++) {
        const long sz = (long)in_sizes[i];
        if (sz == (long)M_DIM * K_DIM) x = (const int*)d_in[i];
        else if (sz == (long)N_DIM * K_DIM) w = (const int*)d_in[i];
        else if (sz == N_DIM) bias = (const int*)d_in[i];
        else if (sz == 1) {
            if (!alpha) alpha = (const float*)d_in[i];
            else beta = (const float*)d_in[i];
        }
    }
    float* out = (float*)d_out;

    dim3 grid(N_DIM / BN, M_DIM / BM);   // (32, 64)
    gemm_dp4a<<<grid, 256>>>(x, w, bias, alpha, beta, out);
}

// round 10
// speedup vs baseline: 4.9101x; 4.9101x over previous
#include <cuda_runtime.h>
#include <cstdint>

// ---------------------------------------------------------------------------
// W8A8B32O32 Linear: D[m,n] = round(alpha * sum_k x[m,k]*W[n,k] + beta*bias[n])
// M=8192, K=4096, N=4096. Inputs int32 holding int8-range values.
// OUTPUT dtype is FLOAT32 (confirmed round 8).
//
// ROUND 10: resubmission of round 9 (broker infra failed twice; never ran).
//   pack int32->int8 scratch, mma.sync.m16n8k32.s8, 3-stage cp.async,
//   80B-padded conflict-free smem rows, float32 epilogue (round-even).
// ---------------------------------------------------------------------------

#define M_DIM 8192
#define N_DIM 4096
#define K_DIM 4096
#define BM 128
#define BN 128
#define BK 64
#define KI (K_DIM / BK)      // 64
#define STAGES 3

#define ROWB 80                            // 64 data bytes + 16 pad (20-bank stride)
#define TILE_BYTES (128 * ROWB)            // 10240 per operand
#define STAGE_BYTES (2 * TILE_BYTES)       // 20480
#define SMEM_TOTAL (STAGES * STAGE_BYTES)  // 61440

// int8 scratch (device globals: allocation-guard safe)
__device__ __align__(1024) int8_t g_x8[(size_t)M_DIM * K_DIM];   // 32 MB
__device__ __align__(1024) int8_t g_w8[(size_t)N_DIM * K_DIM];   // 16 MB

static __device__ __forceinline__ uint32_t smem_u32(const void* p) {
    uint32_t r;
    asm("{ .reg .u64 t; cvta.to.shared.u64 t, %1; cvt.u32.u64 %0, t; }" : "=r"(r) : "l"(p));
    return r;
}

static __device__ __forceinline__ uint32_t lds_u32(uint32_t addr) {
    uint32_t v;
    asm volatile("ld.shared.b32 %0, [%1];" : "=r"(v) : "r"(addr));
    return v;
}

// ---------------------------------------------------------------------------
// Pack kernel: 16 int32 -> 16 int8 per thread (values are int8-range)
// ---------------------------------------------------------------------------
__global__ void __launch_bounds__(256) pack_i32_to_i8(const int* __restrict__ src,
                                                      int8_t* __restrict__ dst, int n16) {
    int i = blockIdx.x * blockDim.x + threadIdx.x;
    if (i >= n16) return;
    const int4* s = reinterpret_cast<const int4*>(src) + (size_t)i * 4;
    int4 v0 = s[0], v1 = s[1], v2 = s[2], v3 = s[3];
    auto pk = [](int4 v) -> uint32_t {
        uint32_t lo = __byte_perm((uint32_t)v.x, (uint32_t)v.y, 0x0040);
        uint32_t hi = __byte_perm((uint32_t)v.z, (uint32_t)v.w, 0x0040);
        return __byte_perm(lo, hi, 0x5410);
    };
    uint4 o = make_uint4(pk(v0), pk(v1), pk(v2), pk(v3));
    reinterpret_cast<uint4*>(dst)[i] = o;
}

// ---------------------------------------------------------------------------
// GEMM: m16n8k32 IMMA, 128x128 CTA tile, 8 warps of 64x32, 3-stage cp.async
// ---------------------------------------------------------------------------
__global__ void __launch_bounds__(256, 1) gemm_i8_imma(
    const int8_t* __restrict__ A8, const int8_t* __restrict__ B8,
    const int* __restrict__ bias, const float* __restrict__ alphap,
    const float* __restrict__ betap, float* __restrict__ out) {
    extern __shared__ char smem[];
    const uint32_t sbase = smem_u32(smem);
    const int tid = threadIdx.x;
    const int wid = tid >> 5;
    const int lane = tid & 31;
    const int warp_m = wid & 1;          // 2 warp rows x 64
    const int warp_n = wid >> 1;         // 4 warp cols x 32
    const int m0 = blockIdx.y * BM;
    const int n0 = blockIdx.x * BN;

    const int8_t* ga = A8 + (size_t)m0 * K_DIM;
    const int8_t* gb = B8 + (size_t)n0 * K_DIM;

    // cp.async mapping: 512 x 16B chunks per operand per stage, 2 each/thread
    const int ld_row0 = tid >> 2;              // 0..63
    const int ld_chunk = (tid & 3) * 16;       // 0/16/32/48
    const uint32_t so0 = (uint32_t)(ld_row0 * ROWB + ld_chunk);
    const uint32_t so1 = (uint32_t)((ld_row0 + 64) * ROWB + ld_chunk);

    auto load_stage = [&](int st, int kiter) {
        const int koff = kiter * BK;
        const uint32_t sA = sbase + st * STAGE_BYTES;
        const uint32_t sB = sA + TILE_BYTES;
        const int8_t* gpa0 = ga + (size_t)ld_row0 * K_DIM + koff + ld_chunk;
        const int8_t* gpa1 = gpa0 + (size_t)64 * K_DIM;
        const int8_t* gpb0 = gb + (size_t)ld_row0 * K_DIM + koff + ld_chunk;
        const int8_t* gpb1 = gpb0 + (size_t)64 * K_DIM;
        asm volatile("cp.async.cg.shared.global [%0], [%1], 16;" :: "r"(sA + so0), "l"(gpa0));
        asm volatile("cp.async.cg.shared.global [%0], [%1], 16;" :: "r"(sA + so1), "l"(gpa1));
        asm volatile("cp.async.cg.shared.global [%0], [%1], 16;" :: "r"(sB + so0), "l"(gpb0));
        asm volatile("cp.async.cg.shared.global [%0], [%1], 16;" :: "r"(sB + so1), "l"(gpb1));
    };

    // Fragment base offsets (within a tile) for this lane (PTX m16n8k32.s8 maps)
    const uint32_t a_base = (uint32_t)((warp_m * 64 + (lane >> 2)) * ROWB + (lane & 3) * 4);
    const uint32_t b_base = (uint32_t)((warp_n * 32 + (lane >> 2)) * ROWB + (lane & 3) * 4);

    int acc[4][4][4];
    #pragma unroll
    for (int i = 0; i < 4; i++)
        #pragma unroll
        for (int j = 0; j < 4; j++)
            #pragma unroll
            for (int r = 0; r < 4; r++) acc[i][j][r] = 0;

    // prologue: fill all 3 stages
    #pragma unroll
    for (int s = 0; s < STAGES; s++) {
        load_stage(s, s);
        asm volatile("cp.async.commit_group;" ::: "memory");
    }

    int st = 0;
    for (int k = 0; k < KI; k++) {
        asm volatile("cp.async.wait_group %0;" :: "n"(STAGES - 1) : "memory");
        __syncthreads();

        const uint32_t sA = sbase + st * STAGE_BYTES;
        const uint32_t sB = sA + TILE_BYTES;

        #pragma unroll
        for (int ks = 0; ks < 2; ks++) {               // two k32 steps per BK=64
            const uint32_t ko = (uint32_t)(ks * 32);
            uint32_t a[4][4];
            #pragma unroll
            for (int mi = 0; mi < 4; mi++) {
                const uint32_t ab = sA + a_base + (uint32_t)(mi * 16 * ROWB) + ko;
                a[mi][0] = lds_u32(ab);
                a[mi][1] = lds_u32(ab + 8 * ROWB);
                a[mi][2] = lds_u32(ab + 16);
                a[mi][3] = lds_u32(ab + 8 * ROWB + 16);
            }
            uint32_t b[4][2];
            #pragma unroll
            for (int ni = 0; ni < 4; ni++) {
                const uint32_t bb = sB + b_base + (uint32_t)(ni * 8 * ROWB) + ko;
                b[ni][0] = lds_u32(bb);
                b[ni][1] = lds_u32(bb + 16);
            }
            #pragma unroll
            for (int mi = 0; mi < 4; mi++) {
                #pragma unroll
                for (int ni = 0; ni < 4; ni++) {
                    asm volatile(
                        "mma.sync.aligned.m16n8k32.row.col.s32.s8.s8.s32 "
                        "{%0,%1,%2,%3}, {%4,%5,%6,%7}, {%8,%9}, {%0,%1,%2,%3};"
                        : "+r"(acc[mi][ni][0]), "+r"(acc[mi][ni][1]),
                          "+r"(acc[mi][ni][2]), "+r"(acc[mi][ni][3])
                        : "r"(a[mi][0]), "r"(a[mi][1]), "r"(a[mi][2]), "r"(a[mi][3]),
                          "r"(b[ni][0]), "r"(b[ni][1]));
                }
            }
        }
        __syncthreads();                               // stage st fully consumed

        if (k + STAGES < KI) load_stage(st, k + STAGES);
        asm volatile("cp.async.commit_group;" ::: "memory");

        st = (st == STAGES - 1) ? 0 : st + 1;
    }

    // ------------------------- epilogue (float32 out) -------------------
    const float av = *alphap;
    const float bv = *betap;
    const int mrow = m0 + warp_m * 64 + (lane >> 2);
    const int ncol = n0 + warp_n * 32 + 2 * (lane & 3);
    #pragma unroll
    for (int mi = 0; mi < 4; mi++) {
        #pragma unroll
        for (int ni = 0; ni < 4; ni++) {
            const int n = ncol + ni * 8;
            const float bb0 = __fmul_rn(bv, (float)bias[n + 0]);
            const float bb1 = __fmul_rn(bv, (float)bias[n + 1]);
            float2 o0, o1;
            o0.x = (float)__float2int_rn(__fadd_rn(__fmul_rn(av, (float)acc[mi][ni][0]), bb0));
            o0.y = (float)__float2int_rn(__fadd_rn(__fmul_rn(av, (float)acc[mi][ni][1]), bb1));
            o1.x = (float)__float2int_rn(__fadd_rn(__fmul_rn(av, (float)acc[mi][ni][2]), bb0));
            o1.y = (float)__float2int_rn(__fadd_rn(__fmul_rn(av, (float)acc[mi][ni][3]), bb1));
            const size_t r0 = (size_t)(mrow + mi * 16) * N_DIM + n;
            const size_t r1 = r0 + (size_t)8 * N_DIM;
            *reinterpret_cast<float2*>(out + r0) = o0;
            *reinterpret_cast<float2*>(out + r1) = o1;
        }
    }
}

// ---------------------------------------------------------------------------
extern "C" void kernel_launch(void* const* d_in, const int* in_sizes, int n_in,
                              void* d_out, int out_size) {
    // Bind inputs BY SIZE (robust to metadata ordering).
    const int* x = nullptr;       // 8192*4096
    const int* w = nullptr;       // 4096*4096
    const int* bias = nullptr;    // 4096
    const float* alpha = nullptr; // 1 (first size-1 input)
    const float* beta = nullptr;  // 1 (second size-1 input)
    for (int i = 0; i < n_in; i++) {
        const long sz = (long)in_sizes[i];
        if (sz == (long)M_DIM * K_DIM) x = (const int*)d_in[i];
        else if (sz == (long)N_DIM * K_DIM) w = (const int*)d_in[i];
        else if (sz == N_DIM) bias = (const int*)d_in[i];
        else if (sz == 1) {
            if (!alpha) alpha = (const float*)d_in[i];
            else beta = (const float*)d_in[i];
        }
    }
    float* out = (float*)d_out;

    void* px = nullptr;
    void* pw = nullptr;
    cudaGetSymbolAddress(&px, g_x8);
    cudaGetSymbolAddress(&pw, g_w8);

    const int nx16 = (M_DIM * (K_DIM / 16));
    const int nw16 = (N_DIM * (K_DIM / 16));
    pack_i32_to_i8<<<(nx16 + 255) / 256, 256>>>(x, (int8_t*)px, nx16);
    pack_i32_to_i8<<<(nw16 + 255) / 256, 256>>>(w, (int8_t*)pw, nw16);

    cudaFuncSetAttribute(gemm_i8_imma,
                         cudaFuncAttributeMaxDynamicSharedMemorySize, SMEM_TOTAL);
    dim3 grid(N_DIM / BN, M_DIM / BM);   // (32, 64)
    gemm_i8_imma<<<grid, 256, SMEM_TOTAL>>>((const int8_t*)px, (const int8_t*)pw,
                                            bias, alpha, beta, out);
}